// round 1
// baseline (speedup 1.0000x reference)
#include <cuda_runtime.h>
#include <cstdint>
#include <math.h>

// GRU: B=32, S=2048, E=256, H=256, fp32.
// 16 independent groups (2 batches each) x 8-CTA cluster (32-wide H slice each).
// Persistent kernel: weights resident in smem, h exchanged via DSMEM + cluster barriers.

#define BB   32
#define SS   2048
#define EE   256
#define HH   256
#define CSZ  8      // cluster size (CTAs per group)
#define NB   2      // batches per group
#define WJ   32     // H-slice width per CTA
#define NT   256    // threads per CTA
#define NGRP 16
#define GRID (NGRP * CSZ)

// smem layout (floats)
#define OFF_W    0                    // 6 matrices * 256 * 32 = 49152
#define OFF_H    49152                // [2 parity][NB][HH] = 1024
#define OFF_RH   (OFF_H + 1024)      // [2 parity][NB][HH] = 1024
#define OFF_X    (OFF_RH + 1024)     // [NB][EE] = 512
#define OFF_P    (OFF_X + 512)       // [4][8][32] partials = 1024
#define OFF_Z    (OFF_P + 1024)      // [NB][WJ] = 64
#define SMEM_FLOATS (OFF_Z + 64)
#define SMEM_BYTES  (SMEM_FLOATS * 4)

extern __shared__ float smem[];

__device__ __forceinline__ uint32_t smem_u32(const void* p) {
    uint32_t a;
    asm("{ .reg .u64 t; cvta.to.shared.u64 t, %1; cvt.u32.u64 %0, t; }"
        : "=r"(a) : "l"(p));
    return a;
}

__device__ __forceinline__ void cluster_sync_() {
    asm volatile("barrier.cluster.arrive.aligned;" ::: "memory");
    asm volatile("barrier.cluster.wait.aligned;"  ::: "memory");
}

// store value into the same smem offset of every CTA in the cluster (incl. self)
__device__ __forceinline__ void push_all(uint32_t laddr, float v) {
#pragma unroll
    for (int r = 0; r < CSZ; r++) {
        uint32_t ra;
        asm volatile("mapa.shared::cluster.u32 %0, %1, %2;"
                     : "=r"(ra) : "r"(laddr), "r"(r));
        asm volatile("st.shared::cluster.f32 [%0], %1;"
                     :: "r"(ra), "f"(v) : "memory");
    }
}

__global__ void __cluster_dims__(CSZ, 1, 1) __launch_bounds__(NT, 1)
gru_persistent(const float* __restrict__ x,   const float* __restrict__ h0,
               const float* __restrict__ Wz,  const float* __restrict__ Uz,
               const float* __restrict__ Wr,  const float* __restrict__ Ur,
               const float* __restrict__ Wh,  const float* __restrict__ Uh,
               float* __restrict__ out)
{
    const int tid   = threadIdx.x;
    const int rank  = blockIdx.x & (CSZ - 1);
    const int grp   = blockIdx.x >> 3;
    const int b0    = grp * NB;
    const int b1    = b0 + 1;
    const int jbase = rank * WJ;

    float* sW  = smem;            // [6][256][32]
    float* sH  = smem + OFF_H;    // [2][NB][HH]
    float* sRH = smem + OFF_RH;   // [2][NB][HH]
    float* sX  = smem + OFF_X;    // [NB][EE]
    float* sP  = smem + OFF_P;    // [4][8][32]
    float* sZ  = smem + OFF_Z;    // [NB][WJ]

    // ---- load weight column slices into smem (coalesced enough; once) ----
    {
        const float* Ws[6] = {Wz, Uz, Wr, Ur, Wh, Uh};
#pragma unroll
        for (int m = 0; m < 6; m++) {
            const float* G = Ws[m];
            for (int i = tid; i < HH * WJ; i += NT) {
                int k = i >> 5, j = i & 31;
                sW[m * (HH * WJ) + i] = G[k * HH + jbase + j];
            }
        }
    }
    // ---- init h (parity 0) : every CTA keeps its own full copy ----
    sH[0 * (NB * HH) + 0 * HH + tid] = h0[b0 * HH + tid];
    sH[0 * (NB * HH) + 1 * HH + tid] = h0[b1 * HH + tid];
    __syncthreads();
    cluster_sync_();

    const uint32_t sH_base  = smem_u32(sH);
    const uint32_t sRH_base = smem_u32(sRH);

    // prefetch x for t=0
    float px0 = x[(b0 * SS + 0) * EE + tid];
    float px1 = x[(b1 * SS + 0) * EE + tid];

    const int j  = tid & 31;
    const int ks = tid >> 5;
    const int k0 = ks * 32;

    for (int t = 0; t < SS; t++) {
        const int par = t & 1;
        const int nxt = par ^ 1;
        float* shA  = sH  + par * (NB * HH);
        float* srhA = sRH + par * (NB * HH);

        // stage current x, then prefetch next step's x (latency off critical path)
        sX[tid]      = px0;
        sX[EE + tid] = px1;
        __syncthreads();
        if (t + 1 < SS) {
            px0 = x[(b0 * SS + t + 1) * EE + tid];
            px1 = x[(b1 * SS + t + 1) * EE + tid];
        }

        // ---- phase A: z and r gate pre-activations (x-proj fused in) ----
        float az0 = 0.f, az1 = 0.f, ar0 = 0.f, ar1 = 0.f;
#pragma unroll 8
        for (int kk = 0; kk < 32; kk++) {
            const int k = k0 + kk;
            const float xv0 = sX[k],        xv1 = sX[EE + k];
            const float hv0 = shA[k],       hv1 = shA[HH + k];
            const float wzv = sW[0 * 8192 + k * 32 + j];
            const float uzv = sW[1 * 8192 + k * 32 + j];
            const float wrv = sW[2 * 8192 + k * 32 + j];
            const float urv = sW[3 * 8192 + k * 32 + j];
            az0 = fmaf(xv0, wzv, az0); az0 = fmaf(hv0, uzv, az0);
            az1 = fmaf(xv1, wzv, az1); az1 = fmaf(hv1, uzv, az1);
            ar0 = fmaf(xv0, wrv, ar0); ar0 = fmaf(hv0, urv, ar0);
            ar1 = fmaf(xv1, wrv, ar1); ar1 = fmaf(hv1, urv, ar1);
        }
        sP[0 * 256 + ks * 32 + j] = az0;
        sP[1 * 256 + ks * 32 + j] = az1;
        sP[2 * 256 + ks * 32 + j] = ar0;
        sP[3 * 256 + ks * 32 + j] = ar1;
        __syncthreads();

        if (tid < 128) {
            const int mb = tid >> 5;        // 0:z-b0 1:z-b1 2:r-b0 3:r-b1
            const int jj = tid & 31;
            float s = 0.f;
#pragma unroll
            for (int q = 0; q < 8; q++) s += sP[mb * 256 + q * 32 + jj];
            const float g = 1.0f / (1.0f + expf(-s));
            const int b = mb & 1;
            if (mb < 2) {
                sZ[b * WJ + jj] = g;
            } else {
                const float rh = g * shA[b * HH + jbase + jj];
                const uint32_t loff =
                    (uint32_t)((par * (NB * HH) + b * HH + jbase + jj) * 4);
                push_all(sRH_base + loff, rh);
            }
        }
        cluster_sync_();   // #1: rh slices visible cluster-wide

        // ---- phase B: candidate h_wave (x-proj fused in) ----
        float ah0 = 0.f, ah1 = 0.f;
#pragma unroll 8
        for (int kk = 0; kk < 32; kk++) {
            const int k = k0 + kk;
            const float xv0 = sX[k],   xv1 = sX[EE + k];
            const float rv0 = srhA[k], rv1 = srhA[HH + k];
            const float whv = sW[4 * 8192 + k * 32 + j];
            const float uhv = sW[5 * 8192 + k * 32 + j];
            ah0 = fmaf(xv0, whv, ah0); ah0 = fmaf(rv0, uhv, ah0);
            ah1 = fmaf(xv1, whv, ah1); ah1 = fmaf(rv1, uhv, ah1);
        }
        sP[0 * 256 + ks * 32 + j] = ah0;
        sP[1 * 256 + ks * 32 + j] = ah1;
        __syncthreads();

        if (tid < 64) {
            const int b  = tid >> 5;
            const int jj = tid & 31;
            float s = 0.f;
#pragma unroll
            for (int q = 0; q < 8; q++) s += sP[b * 256 + q * 32 + jj];
            const float hw   = tanhf(s);
            const float z    = sZ[b * WJ + jj];
            const float hold = shA[b * HH + jbase + jj];
            const float hnew = (1.0f - z) * hold + z * hw;
            const int bg = (b == 0) ? b0 : b1;
            out[(bg * SS + t) * HH + jbase + jj] = hnew;
            const uint32_t loff =
                (uint32_t)((nxt * (NB * HH) + b * HH + jbase + jj) * 4);
            push_all(sH_base + loff, hnew);
        }
        cluster_sync_();   // #2: h_{t+1} visible cluster-wide
    }
}

extern "C" void kernel_launch(void* const* d_in, const int* in_sizes, int n_in,
                              void* d_out, int out_size)
{
    (void)in_sizes; (void)n_in; (void)out_size;
    const float* x  = (const float*)d_in[0];
    const float* h0 = (const float*)d_in[1];
    const float* Wz = (const float*)d_in[2];
    const float* Uz = (const float*)d_in[3];
    const float* Wr = (const float*)d_in[4];
    const float* Ur = (const float*)d_in[5];
    const float* Wh = (const float*)d_in[6];
    const float* Uh = (const float*)d_in[7];
    float* out = (float*)d_out;

    cudaFuncSetAttribute(gru_persistent,
                         cudaFuncAttributeMaxDynamicSharedMemorySize, SMEM_BYTES);
    gru_persistent<<<GRID, NT, SMEM_BYTES>>>(x, h0, Wz, Uz, Wr, Ur, Wh, Uh, out);
}

// round 4
// speedup vs baseline: 1.5316x; 1.5316x over previous
#include <cuda_runtime.h>
#include <cstdint>
#include <math.h>

// GRU: B=32, S=2048, E=256, H=256, fp32.
// 16 groups (2 batches each) x 8-CTA cluster; each CTA owns a 32-wide H slice.
// U matrices in REGISTERS (96/thread), W matrices in smem.
// h / r*h exchanged via st.async + double-buffered mbarrier tx accounting.

#define SS   2048
#define EE   256
#define HH   256
#define CSZ  8
#define NB   2
#define WJ   32
#define NT   256
#define NGRP 16
#define GRID (NGRP * CSZ)

// smem layout (floats)
#define OFF_WZ 0
#define OFF_WR 8192
#define OFF_WH 16384
#define OFF_H  24576                 // [2][NB][HH] = 1024
#define OFF_RH (OFF_H + 2*NB*HH)     // 25600, [2][NB][HH] = 1024
#define OFF_X  (OFF_RH + 2*NB*HH)    // 26624, [NB][EE] = 512
#define OFF_P  (OFF_X + NB*EE)       // 27136, [4][256] = 1024
#define OFF_MB (OFF_P + 4*256)       // 28160, 4 mbarriers (u64) = 8 floats
#define SMEM_FLOATS (OFF_MB + 8)
#define SMEM_BYTES  (SMEM_FLOATS * 4)

extern __shared__ float smem[];

__device__ __forceinline__ uint32_t smem_u32(const void* p) {
    uint32_t a;
    asm("{ .reg .u64 t; cvta.to.shared.u64 t, %1; cvt.u32.u64 %0, t; }"
        : "=r"(a) : "l"(p));
    return a;
}
__device__ __forceinline__ void mbar_init(uint32_t a, uint32_t cnt) {
    asm volatile("mbarrier.init.shared.b64 [%0], %1;" :: "r"(a), "r"(cnt) : "memory");
}
__device__ __forceinline__ void mbar_expect(uint32_t a, uint32_t bytes) {
    asm volatile("mbarrier.arrive.expect_tx.shared.b64 _, [%0], %1;"
                 :: "r"(a), "r"(bytes) : "memory");
}
__device__ __forceinline__ void mbar_wait(uint32_t a, uint32_t parity) {
    asm volatile(
        "{\n\t.reg .pred P1;\n\t"
        "WL_%=:\n\t"
        "mbarrier.try_wait.parity.acquire.cta.shared::cta.b64 P1, [%0], %1, 0x989680;\n\t"
        "@P1 bra.uni WD_%=;\n\t"
        "bra.uni WL_%=;\n\t"
        "WD_%=:\n\t}"
        :: "r"(a), "r"(parity) : "memory");
}
__device__ __forceinline__ void st_async_f32(uint32_t addr, float v, uint32_t mbar) {
    asm volatile("st.async.shared::cluster.mbarrier::complete_tx::bytes.f32 [%0], %1, [%2];"
                 :: "r"(addr), "f"(v), "r"(mbar) : "memory");
}
__device__ __forceinline__ void cluster_sync_() {
    asm volatile("barrier.cluster.arrive.aligned;" ::: "memory");
    asm volatile("barrier.cluster.wait.aligned;"  ::: "memory");
}

// acc pair for 2 batches: U from registers, W (x-projection) from smem.
__device__ __forceinline__ void matvec_pair(
    const float* __restrict__ hv0, const float* __restrict__ hv1,
    const float* __restrict__ xv0, const float* __restrict__ xv1,
    const float* __restrict__ sW, const float (&u)[32],
    int k0, int j, float& a0, float& a1)
{
    const float4* H0 = (const float4*)hv0;
    const float4* H1 = (const float4*)hv1;
    const float4* X0 = (const float4*)xv0;
    const float4* X1 = (const float4*)xv1;
    const int q0 = k0 >> 2;
    float s0 = 0.f, s1 = 0.f;
#pragma unroll
    for (int q = 0; q < 8; q++) {
        float4 ha = H0[q0 + q], hb = H1[q0 + q];
        float4 xa = X0[q0 + q], xb = X1[q0 + q];
        const float* wp = sW + (k0 + q * 4) * WJ + j;
        const float w0 = wp[0], w1 = wp[32], w2 = wp[64], w3 = wp[96];
        s0 = fmaf(ha.x, u[q*4+0], s0);  s1 = fmaf(hb.x, u[q*4+0], s1);
        s0 = fmaf(xa.x, w0, s0);        s1 = fmaf(xb.x, w0, s1);
        s0 = fmaf(ha.y, u[q*4+1], s0);  s1 = fmaf(hb.y, u[q*4+1], s1);
        s0 = fmaf(xa.y, w1, s0);        s1 = fmaf(xb.y, w1, s1);
        s0 = fmaf(ha.z, u[q*4+2], s0);  s1 = fmaf(hb.z, u[q*4+2], s1);
        s0 = fmaf(xa.z, w2, s0);        s1 = fmaf(xb.z, w2, s1);
        s0 = fmaf(ha.w, u[q*4+3], s0);  s1 = fmaf(hb.w, u[q*4+3], s1);
        s0 = fmaf(xa.w, w3, s0);        s1 = fmaf(xb.w, w3, s1);
    }
    a0 = s0; a1 = s1;
}

__global__ void __cluster_dims__(CSZ, 1, 1) __launch_bounds__(NT, 1)
gru_persistent(const float* __restrict__ x,  const float* __restrict__ h0,
               const float* __restrict__ Wz, const float* __restrict__ Uz,
               const float* __restrict__ Wr, const float* __restrict__ Ur,
               const float* __restrict__ Wh, const float* __restrict__ Uh,
               float* __restrict__ out)
{
    const int tid   = threadIdx.x;
    const int rank  = blockIdx.x & (CSZ - 1);
    const int grp   = blockIdx.x >> 3;
    const int b0    = grp * NB;
    const int b1    = b0 + 1;
    const int jbase = rank * WJ;
    const int j     = tid & 31;
    const int ks    = tid >> 5;
    const int k0    = ks * 32;
    const int jcol  = jbase + j;

    float* sWz = smem + OFF_WZ;
    float* sWr = smem + OFF_WR;
    float* sWh = smem + OFF_WH;
    float* sH  = smem + OFF_H;
    float* sRH = smem + OFF_RH;
    float* sX  = smem + OFF_X;
    float* sP  = smem + OFF_P;

    const uint32_t base_u = smem_u32(smem);
    const uint32_t mb_rh0 = base_u + OFF_MB * 4;
    const uint32_t mb_h0  = base_u + OFF_MB * 4 + 16;

    // ---- U weight slices into registers ----
    float uz[32], ur[32], uh[32];
#pragma unroll
    for (int kk = 0; kk < 32; kk++) {
        uz[kk] = Uz[(k0 + kk) * HH + jcol];
        ur[kk] = Ur[(k0 + kk) * HH + jcol];
        uh[kk] = Uh[(k0 + kk) * HH + jcol];
    }
    // ---- W slices into smem ----
    for (int i = tid; i < HH * WJ; i += NT) {
        int k = i >> 5, jj = i & 31;
        sWz[i] = Wz[k * HH + jbase + jj];
        sWr[i] = Wr[k * HH + jbase + jj];
        sWh[i] = Wh[k * HH + jbase + jj];
    }
    // ---- h0 into parity-0 buffer ----
    sH[0 * HH + tid]  = h0[b0 * HH + tid];
    sH[1 * HH + tid]  = h0[b1 * HH + tid];   // NB*HH layout: [b][HH]
    if (tid == 0) {
        mbar_init(mb_rh0, 1); mbar_init(mb_rh0 + 8, 1);
        mbar_init(mb_h0, 1);  mbar_init(mb_h0 + 8, 1);
    }
    __syncthreads();
    cluster_sync_();   // mbarriers + readiness visible cluster-wide

    uint32_t peer[CSZ];
#pragma unroll
    for (int r = 0; r < CSZ; r++) {
        asm volatile("mapa.shared::cluster.u32 %0, %1, %2;"
                     : "=r"(peer[r]) : "r"(base_u), "r"(r));
    }

    float px0 = x[(size_t)b0 * SS * EE + tid];
    float px1 = x[(size_t)b1 * SS * EE + tid];

    for (int t = 0; t < SS; t++) {
        const int par = t & 1;
        const int nxt = par ^ 1;
        float* shA  = sH  + par * NB * HH;
        float* srhA = sRH + par * NB * HH;

        if (tid == 0) {
            mbar_expect(mb_rh0 + par * 8, NB * HH * 4);
            if (t + 1 < SS) mbar_expect(mb_h0 + nxt * 8, NB * HH * 4);
        }
        if (t > 0) {
            const uint32_t p_h = (uint32_t)(((t - 2 + par) >> 1) & 1);
            mbar_wait(mb_h0 + par * 8, p_h);      // h_t fully arrived
        }
        sX[tid]      = px0;
        sX[EE + tid] = px1;
        __syncthreads();
        if (t + 1 < SS) {
            px0 = x[((size_t)b0 * SS + t + 1) * EE + tid];
            px1 = x[((size_t)b1 * SS + t + 1) * EE + tid];
        }

        // ---- phase A: r pre-activation ----
        float ar0, ar1;
        matvec_pair(shA, shA + HH, sX, sX + EE, sWr, ur, k0, j, ar0, ar1);
        sP[tid] = ar0; sP[256 + tid] = ar1;
        __syncthreads();

        if (tid < 64) {
            const int b = tid >> 5, jj = tid & 31;
            float s = 0.f;
#pragma unroll
            for (int q = 0; q < 8; q++) s += sP[b * 256 + q * 32 + jj];
            const float r  = 1.0f / (1.0f + expf(-s));
            const float rh = r * shA[b * HH + jbase + jj];
            const uint32_t off  = (uint32_t)(OFF_RH + par * NB * HH + b * HH + jbase + jj) * 4;
            const uint32_t moff = (uint32_t)(OFF_MB * 4) + (uint32_t)(par * 8);
#pragma unroll
            for (int rr = 0; rr < CSZ; rr++)
                st_async_f32(peer[rr] + off, rh, peer[rr] + moff);
        }

        // ---- phase A': z pre-activation (hides rh flight) ----
        float az0, az1;
        matvec_pair(shA, shA + HH, sX, sX + EE, sWz, uz, k0, j, az0, az1);
        sP[2 * 256 + tid] = az0; sP[3 * 256 + tid] = az1;

        mbar_wait(mb_rh0 + par * 8, (uint32_t)((t >> 1) & 1));  // r*h arrived

        // ---- phase B: candidate ----
        float ah0, ah1;
        matvec_pair(srhA, srhA + HH, sX, sX + EE, sWh, uh, k0, j, ah0, ah1);
        sP[tid] = ah0; sP[256 + tid] = ah1;
        __syncthreads();

        if (tid < 64) {
            const int b = tid >> 5, jj = tid & 31;
            float sh_ = 0.f, sz_ = 0.f;
#pragma unroll
            for (int q = 0; q < 8; q++) {
                sh_ += sP[b * 256 + q * 32 + jj];
                sz_ += sP[(2 + b) * 256 + q * 32 + jj];
            }
            const float z    = 1.0f / (1.0f + expf(-sz_));
            const float hw   = tanhf(sh_);
            const float hold = shA[b * HH + jbase + jj];
            const float hnew = (1.0f - z) * hold + z * hw;
            out[((size_t)(b0 + b) * SS + t) * HH + jbase + jj] = hnew;
            if (t + 1 < SS) {
                const uint32_t off  = (uint32_t)(OFF_H + nxt * NB * HH + b * HH + jbase + jj) * 4;
                const uint32_t moff = (uint32_t)(OFF_MB * 4 + 16) + (uint32_t)(nxt * 8);
#pragma unroll
                for (int rr = 0; rr < CSZ; rr++)
                    st_async_f32(peer[rr] + off, hnew, peer[rr] + moff);
            }
        }
    }
    cluster_sync_();   // no CTA exits while inbound traffic could be in flight
}

extern "C" void kernel_launch(void* const* d_in, const int* in_sizes, int n_in,
                              void* d_out, int out_size)
{
    (void)in_sizes; (void)n_in; (void)out_size;
    const float* x  = (const float*)d_in[0];
    const float* h0 = (const float*)d_in[1];
    const float* Wz = (const float*)d_in[2];
    const float* Uz = (const float*)d_in[3];
    const float* Wr = (const float*)d_in[4];
    const float* Ur = (const float*)d_in[5];
    const float* Wh = (const float*)d_in[6];
    const float* Uh = (const float*)d_in[7];
    float* out = (float*)d_out;

    cudaFuncSetAttribute(gru_persistent,
                         cudaFuncAttributeMaxDynamicSharedMemorySize, SMEM_BYTES);
    gru_persistent<<<GRID, NT, SMEM_BYTES>>>(x, h0, Wz, Uz, Wr, Ur, Wh, Uh, out);
}

// round 9
// speedup vs baseline: 1.7492x; 1.1420x over previous
#include <cuda_runtime.h>
#include <cstdint>
#include <math.h>

// GRU: B=32, S=2048, E=256, H=256, fp32.
// 16 groups (2 batches) x 8-CTA cluster; CTA owns 32-wide H slice.
// ALL weights in registers (96 x b64 / thread), FFMA2 (f32x2) math,
// st.async.b64 exchanges hidden behind independent x-projection FMA work.

#define SS   2048
#define EE   256
#define HH   256
#define CSZ  8
#define NB   2
#define NT   256
#define NGRP 16
#define GRID (NGRP * CSZ)

typedef unsigned long long u64;

// smem layout (floats)
#define OFF_H   0                  // [2][NB][HH] = 1024
#define OFF_RH  1024               // [2][NB][HH] = 1024
#define OFF_X   2048               // [2][NB][EE] = 1024
#define OFF_P   3072               // [6][256]    = 1536
#define OFF_Z   4608               // [NB][32]    = 64
#define OFF_MB  4672               // 4 mbarriers = 8 floats
#define SMEM_FLOATS (OFF_MB + 8)
#define SMEM_BYTES  (SMEM_FLOATS * 4)

extern __shared__ float smem[];

__device__ __forceinline__ uint32_t smem_u32(const void* p) {
    uint32_t a;
    asm("{ .reg .u64 t; cvta.to.shared.u64 t, %1; cvt.u32.u64 %0, t; }"
        : "=r"(a) : "l"(p));
    return a;
}
__device__ __forceinline__ void mbar_init(uint32_t a, uint32_t cnt) {
    asm volatile("mbarrier.init.shared.b64 [%0], %1;" :: "r"(a), "r"(cnt) : "memory");
}
__device__ __forceinline__ void mbar_expect(uint32_t a, uint32_t bytes) {
    asm volatile("mbarrier.arrive.expect_tx.shared.b64 _, [%0], %1;"
                 :: "r"(a), "r"(bytes) : "memory");
}
__device__ __forceinline__ void mbar_wait(uint32_t a, uint32_t parity) {
    asm volatile(
        "{\n\t.reg .pred P1;\n\t"
        "WL_%=:\n\t"
        "mbarrier.try_wait.parity.acquire.cta.shared::cta.b64 P1, [%0], %1, 0x989680;\n\t"
        "@P1 bra.uni WD_%=;\n\t"
        "bra.uni WL_%=;\n\t"
        "WD_%=:\n\t}"
        :: "r"(a), "r"(parity) : "memory");
}
__device__ __forceinline__ void cluster_sync_() {
    asm volatile("barrier.cluster.arrive.aligned;" ::: "memory");
    asm volatile("barrier.cluster.wait.aligned;"  ::: "memory");
}
__device__ __forceinline__ u64 pk(float lo, float hi) {
    u64 r; asm("mov.b64 %0, {%1, %2};" : "=l"(r) : "f"(lo), "f"(hi)); return r;
}
__device__ __forceinline__ float hsum(u64 v) {
    float a, b; asm("mov.b64 {%0, %1}, %2;" : "=f"(a), "=f"(b) : "l"(v));
    return a + b;
}
__device__ __forceinline__ void ffma2(u64& d, u64 a, u64 b) {
    asm("fma.rn.f32x2 %0, %1, %2, %0;" : "+l"(d) : "l"(a), "l"(b));
}
// send packed 8B to same offset in all cluster CTAs with tx accounting
__device__ __forceinline__ void push8_b64(uint32_t base_u, uint32_t off_b,
                                          u64 v, uint32_t moff_b) {
#pragma unroll
    for (int r = 0; r < CSZ; r++) {
        uint32_t ra;
        asm volatile("mapa.shared::cluster.u32 %0, %1, %2;"
                     : "=r"(ra) : "r"(base_u), "r"(r));
        asm volatile("st.async.shared::cluster.mbarrier::complete_tx::bytes.b64 "
                     "[%0], %1, [%2];"
                     :: "r"(ra + off_b), "l"(v), "r"(ra + moff_b) : "memory");
    }
}

__global__ void __cluster_dims__(CSZ, 1, 1) __launch_bounds__(NT, 1)
gru_persistent(const float* __restrict__ x,  const float* __restrict__ h0,
               const float* __restrict__ Wz, const float* __restrict__ Uz,
               const float* __restrict__ Wr, const float* __restrict__ Ur,
               const float* __restrict__ Wh, const float* __restrict__ Uh,
               float* __restrict__ out)
{
    const int tid   = threadIdx.x;
    const int rank  = blockIdx.x & (CSZ - 1);
    const int grp   = blockIdx.x >> 3;
    const int b0    = grp * NB;
    const int b1    = b0 + 1;
    const int jbase = rank * 32;
    const int j     = tid & 31;
    const int ks    = tid >> 5;
    const int k0    = ks * 32;
    const int kq0   = ks * 8;              // float4 chunk base
    const int jcol  = jbase + j;

    float* sH  = smem + OFF_H;
    float* sRH = smem + OFF_RH;
    float* sX  = smem + OFF_X;
    float* sP  = smem + OFF_P;
    float* sZ  = smem + OFF_Z;

    const uint32_t base_u = smem_u32(smem);
    const uint32_t mb_rh  = base_u + OFF_MB * 4;        // +par*8
    const uint32_t mb_h   = base_u + OFF_MB * 4 + 16;   // +par*8

    // ---- ALL weight slices into registers (k-pairs packed for FFMA2) ----
    u64 wz2[16], uz2[16], wr2[16], ur2[16], wh2[16], uh2[16];
#pragma unroll
    for (int p = 0; p < 16; p++) {
        const int k = k0 + 2 * p;
        wz2[p] = pk(Wz[k * HH + jcol], Wz[(k + 1) * HH + jcol]);
        uz2[p] = pk(Uz[k * HH + jcol], Uz[(k + 1) * HH + jcol]);
        wr2[p] = pk(Wr[k * HH + jcol], Wr[(k + 1) * HH + jcol]);
        ur2[p] = pk(Ur[k * HH + jcol], Ur[(k + 1) * HH + jcol]);
        wh2[p] = pk(Wh[k * HH + jcol], Wh[(k + 1) * HH + jcol]);
        uh2[p] = pk(Uh[k * HH + jcol], Uh[(k + 1) * HH + jcol]);
    }
    // ---- h0 into parity-0 buffer; x(0) staged ----
    sH[tid]        = h0[b0 * HH + tid];
    sH[HH + tid]   = h0[b1 * HH + tid];
    sX[tid]        = x[(size_t)b0 * SS * EE + tid];
    sX[EE + tid]   = x[(size_t)b1 * SS * EE + tid];
    if (tid == 0) {
        mbar_init(mb_rh, 1); mbar_init(mb_rh + 8, 1);
        mbar_init(mb_h, 1);  mbar_init(mb_h + 8, 1);
    }
    __syncthreads();
    cluster_sync_();

    float px0 = x[((size_t)b0 * SS + 1) * EE + tid];
    float px1 = x[((size_t)b1 * SS + 1) * EE + tid];

    for (int t = 0; t < SS; t++) {
        const int par = t & 1;
        const int nxt = par ^ 1;
        float* shA  = sH  + par * (NB * HH);
        float* srhA = sRH + par * (NB * HH);
        const float4* Xc = (const float4*)(sX + par * (NB * EE));

        if (tid == 0) {
            mbar_expect(mb_rh + par * 8, NB * HH * 4);
            if (t + 1 < SS) mbar_expect(mb_h + nxt * 8, NB * HH * 4);
        }

        // ---- phase 1: x @ {Wz, Wr} (independent of h -> hides h flight) ----
        u64 az0 = 0, az1 = 0, ar0 = 0, ar1 = 0;
#pragma unroll
        for (int q = 0; q < 8; q++) {
            float4 xa = Xc[kq0 + q], xb = Xc[64 + kq0 + q];
            u64 xa0 = pk(xa.x, xa.y), xa1 = pk(xa.z, xa.w);
            u64 xb0 = pk(xb.x, xb.y), xb1 = pk(xb.z, xb.w);
            ffma2(az0, xa0, wz2[2*q]); ffma2(az0, xa1, wz2[2*q+1]);
            ffma2(az1, xb0, wz2[2*q]); ffma2(az1, xb1, wz2[2*q+1]);
            ffma2(ar0, xa0, wr2[2*q]); ffma2(ar0, xa1, wr2[2*q+1]);
            ffma2(ar1, xb0, wr2[2*q]); ffma2(ar1, xb1, wr2[2*q+1]);
        }

        if (t > 0) mbar_wait(mb_h + par * 8, (uint32_t)(((t - 2 + par) >> 1) & 1));

        // ---- phase 3: h @ {Uz, Ur} ----
        const float4* Hc = (const float4*)shA;
#pragma unroll
        for (int q = 0; q < 8; q++) {
            float4 ha = Hc[kq0 + q], hb = Hc[64 + kq0 + q];
            u64 ha0 = pk(ha.x, ha.y), ha1 = pk(ha.z, ha.w);
            u64 hb0 = pk(hb.x, hb.y), hb1 = pk(hb.z, hb.w);
            ffma2(az0, ha0, uz2[2*q]); ffma2(az0, ha1, uz2[2*q+1]);
            ffma2(az1, hb0, uz2[2*q]); ffma2(az1, hb1, uz2[2*q+1]);
            ffma2(ar0, ha0, ur2[2*q]); ffma2(ar0, ha1, ur2[2*q+1]);
            ffma2(ar1, hb0, ur2[2*q]); ffma2(ar1, hb1, ur2[2*q+1]);
        }
        sP[tid]       = hsum(az0);
        sP[256 + tid] = hsum(az1);
        sP[512 + tid] = hsum(ar0);
        sP[768 + tid] = hsum(ar1);
        __syncthreads();

        // ---- mid reduce: z kept local, r*h pushed cluster-wide (b64 packed) --
        if (tid < 128) {
            const int mb = tid >> 5, jj = tid & 31;
            float s = 0.f;
#pragma unroll
            for (int q = 0; q < 8; q++) s += sP[mb * 256 + q * 32 + jj];
            const float g = __fdividef(1.f, 1.f + __expf(-s));
            if (mb < 2) {
                sZ[mb * 32 + jj] = g;
            } else {
                const int b = mb - 2;
                const float rh  = g * shA[b * HH + jbase + jj];
                const float rhh = __shfl_down_sync(0xffffffffu, rh, 1);
                if ((jj & 1) == 0) {
                    const uint32_t off =
                        (uint32_t)(OFF_RH + par * (NB * HH) + b * HH + jbase + jj) * 4;
                    push8_b64(base_u, off, pk(rh, rhh),
                              (uint32_t)(OFF_MB * 4) + (uint32_t)(par * 8));
                }
            }
        }

        // ---- phase 5: x @ Wh (independent of rh -> hides rh flight) ----
        u64 ah0 = 0, ah1 = 0;
#pragma unroll
        for (int q = 0; q < 8; q++) {
            float4 xa = Xc[kq0 + q], xb = Xc[64 + kq0 + q];
            u64 xa0 = pk(xa.x, xa.y), xa1 = pk(xa.z, xa.w);
            u64 xb0 = pk(xb.x, xb.y), xb1 = pk(xb.z, xb.w);
            ffma2(ah0, xa0, wh2[2*q]); ffma2(ah0, xa1, wh2[2*q+1]);
            ffma2(ah1, xb0, wh2[2*q]); ffma2(ah1, xb1, wh2[2*q+1]);
        }

        mbar_wait(mb_rh + par * 8, (uint32_t)((t >> 1) & 1));

        // ---- phase 7: (r*h) @ Uh ----
        const float4* Rc = (const float4*)srhA;
#pragma unroll
        for (int q = 0; q < 8; q++) {
            float4 ra = Rc[kq0 + q], rb = Rc[64 + kq0 + q];
            u64 ra0 = pk(ra.x, ra.y), ra1 = pk(ra.z, ra.w);
            u64 rb0 = pk(rb.x, rb.y), rb1 = pk(rb.z, rb.w);
            ffma2(ah0, ra0, uh2[2*q]); ffma2(ah0, ra1, uh2[2*q+1]);
            ffma2(ah1, rb0, uh2[2*q]); ffma2(ah1, rb1, uh2[2*q+1]);
        }
        sP[1024 + tid] = hsum(ah0);
        sP[1280 + tid] = hsum(ah1);
        // stage x(t+1) into the other parity buffer (no readers conflict)
        if (t + 1 < SS) {
            sX[nxt * (NB * EE) + tid]      = px0;
            sX[nxt * (NB * EE) + EE + tid] = px1;
        }
        __syncthreads();

        // ---- final: tanh, combine, output, push h(t+1) ----
        if (tid < 64) {
            const int b = tid >> 5, jj = tid & 31;
            float s = 0.f;
#pragma unroll
            for (int q = 0; q < 8; q++) s += sP[1024 + b * 256 + q * 32 + jj];
            const float hw   = 1.f - __fdividef(2.f, __expf(2.f * s) + 1.f);
            const float z    = sZ[b * 32 + jj];
            const float hold = shA[b * HH + jbase + jj];
            const float hnew = fmaf(z, hw - hold, hold);
            out[((size_t)(b0 + b) * SS + t) * HH + jbase + jj] = hnew;
            if (t + 1 < SS) {
                const float hh = __shfl_down_sync(0xffffffffu, hnew, 1);
                if ((jj & 1) == 0) {
                    const uint32_t off =
                        (uint32_t)(OFF_H + nxt * (NB * HH) + b * HH + jbase + jj) * 4;
                    push8_b64(base_u, off, pk(hnew, hh),
                              (uint32_t)(OFF_MB * 4 + 16) + (uint32_t)(nxt * 8));
                }
            }
        }
        // prefetch x(t+2)
        if (t + 2 < SS) {
            px0 = x[((size_t)b0 * SS + t + 2) * EE + tid];
            px1 = x[((size_t)b1 * SS + t + 2) * EE + tid];
        }
    }
    cluster_sync_();   // no CTA exits while inbound traffic could be in flight
}

extern "C" void kernel_launch(void* const* d_in, const int* in_sizes, int n_in,
                              void* d_out, int out_size)
{
    (void)in_sizes; (void)n_in; (void)out_size;
    const float* x  = (const float*)d_in[0];
    const float* h0 = (const float*)d_in[1];
    const float* Wz = (const float*)d_in[2];
    const float* Uz = (const float*)d_in[3];
    const float* Wr = (const float*)d_in[4];
    const float* Ur = (const float*)d_in[5];
    const float* Wh = (const float*)d_in[6];
    const float* Uh = (const float*)d_in[7];
    float* out = (float*)d_out;

    cudaFuncSetAttribute(gru_persistent,
                         cudaFuncAttributeMaxDynamicSharedMemorySize, SMEM_BYTES);
    gru_persistent<<<GRID, NT, SMEM_BYTES>>>(x, h0, Wz, Uz, Wr, Ur, Wh, Uh, out);
}

// round 10
// speedup vs baseline: 1.8901x; 1.0806x over previous
#include <cuda_runtime.h>
#include <cstdint>
#include <math.h>

// GRU: B=32, S=2048, E=256, H=256, fp32.
// 16 groups (2 batches) x 8-CTA cluster; CTA owns 32-wide H slice.
// U matrices in registers (48 x b64), W matrices PRE-PACKED f32x2 in smem.
// All vector operands loaded as LDS.64 (no pack movs). FFMA2 math.
// h / r*h exchanged via st.async.b64 + double-buffered mbarrier tx accounting.

#define SS   2048
#define EE   256
#define HH   256
#define CSZ  8
#define NB   2
#define NT   256
#define NGRP 16
#define GRID (NGRP * CSZ)

typedef unsigned long long u64;

// smem layout (floats)
#define OFF_W   0                    // 3 * 128 * 32 u64 = 24576 floats (96 KB)
#define OFF_H   24576                // [2][NB][HH] = 1024
#define OFF_RH  (OFF_H + 1024)       // 1024
#define OFF_X   (OFF_RH + 1024)      // [2][NB][EE] = 1024
#define OFF_P   (OFF_X + 1024)       // [6][256] = 1536
#define OFF_Z   (OFF_P + 1536)       // [NB][32] = 64
#define OFF_MB  (OFF_Z + 64)         // 4 mbarriers = 8 floats
#define SMEM_FLOATS (OFF_MB + 8)
#define SMEM_BYTES  (SMEM_FLOATS * 4)

extern __shared__ float smem[];

__device__ __forceinline__ uint32_t smem_u32(const void* p) {
    uint32_t a;
    asm("{ .reg .u64 t; cvta.to.shared.u64 t, %1; cvt.u32.u64 %0, t; }"
        : "=r"(a) : "l"(p));
    return a;
}
__device__ __forceinline__ void mbar_init(uint32_t a, uint32_t cnt) {
    asm volatile("mbarrier.init.shared.b64 [%0], %1;" :: "r"(a), "r"(cnt) : "memory");
}
__device__ __forceinline__ void mbar_expect(uint32_t a, uint32_t bytes) {
    asm volatile("mbarrier.arrive.expect_tx.shared.b64 _, [%0], %1;"
                 :: "r"(a), "r"(bytes) : "memory");
}
__device__ __forceinline__ void mbar_wait(uint32_t a, uint32_t parity) {
    asm volatile(
        "{\n\t.reg .pred P1;\n\t"
        "WL_%=:\n\t"
        "mbarrier.try_wait.parity.acquire.cta.shared::cta.b64 P1, [%0], %1, 0x989680;\n\t"
        "@P1 bra.uni WD_%=;\n\t"
        "bra.uni WL_%=;\n\t"
        "WD_%=:\n\t}"
        :: "r"(a), "r"(parity) : "memory");
}
__device__ __forceinline__ void cluster_sync_() {
    asm volatile("barrier.cluster.arrive.aligned;" ::: "memory");
    asm volatile("barrier.cluster.wait.aligned;"  ::: "memory");
}
__device__ __forceinline__ u64 pk(float lo, float hi) {
    u64 r; asm("mov.b64 %0, {%1, %2};" : "=l"(r) : "f"(lo), "f"(hi)); return r;
}
__device__ __forceinline__ float hsum(u64 v) {
    float a, b; asm("mov.b64 {%0, %1}, %2;" : "=f"(a), "=f"(b) : "l"(v));
    return a + b;
}
__device__ __forceinline__ void ffma2(u64& d, u64 a, u64 b) {
    asm("fma.rn.f32x2 %0, %1, %2, %0;" : "+l"(d) : "l"(a), "l"(b));
}
// send packed 8B to same offset in all cluster CTAs with tx accounting
__device__ __forceinline__ void push8_b64(uint32_t base_u, uint32_t off_b,
                                          u64 v, uint32_t moff_b) {
#pragma unroll
    for (int r = 0; r < CSZ; r++) {
        uint32_t ra;
        asm volatile("mapa.shared::cluster.u32 %0, %1, %2;"
                     : "=r"(ra) : "r"(base_u), "r"(r));
        asm volatile("st.async.shared::cluster.mbarrier::complete_tx::bytes.b64 "
                     "[%0], %1, [%2];"
                     :: "r"(ra + off_b), "l"(v), "r"(ra + moff_b) : "memory");
    }
}

__global__ void __cluster_dims__(CSZ, 1, 1) __launch_bounds__(NT, 1)
gru_persistent(const float* __restrict__ x,  const float* __restrict__ h0,
               const float* __restrict__ Wz, const float* __restrict__ Uz,
               const float* __restrict__ Wr, const float* __restrict__ Ur,
               const float* __restrict__ Wh, const float* __restrict__ Uh,
               float* __restrict__ out)
{
    const int tid   = threadIdx.x;
    const int rank  = blockIdx.x & (CSZ - 1);
    const int grp   = blockIdx.x >> 3;
    const int b0    = grp * NB;
    const int b1    = b0 + 1;
    const int jbase = rank * 32;
    const int j     = tid & 31;
    const int ks    = tid >> 5;
    const int k0    = ks * 32;
    const int ksk   = ks * 16;          // kpair base for this thread
    const int jcol  = jbase + j;

    u64*   sW64 = (u64*)smem;                    // [3][128][32] u64
    float* sH   = smem + OFF_H;
    float* sRH  = smem + OFF_RH;
    float* sX   = smem + OFF_X;
    float* sP   = smem + OFF_P;
    float* sZ   = smem + OFF_Z;

    const uint32_t base_u = smem_u32(smem);
    const uint32_t mb_rh  = base_u + OFF_MB * 4;        // +par*8
    const uint32_t mb_h   = base_u + OFF_MB * 4 + 16;   // +par*8

    // ---- U slices into registers (k-pairs packed for FFMA2): 48 u64 ----
    u64 uz2[16], ur2[16], uh2[16];
#pragma unroll
    for (int p = 0; p < 16; p++) {
        const int k = k0 + 2 * p;
        uz2[p] = pk(Uz[k * HH + jcol], Uz[(k + 1) * HH + jcol]);
        ur2[p] = pk(Ur[k * HH + jcol], Ur[(k + 1) * HH + jcol]);
        uh2[p] = pk(Uh[k * HH + jcol], Uh[(k + 1) * HH + jcol]);
    }
    // ---- W slices pre-packed f32x2 into smem: sW64[g][kp][j] ----
    {
        const float* Ws[3] = {Wz, Wr, Wh};
        for (int i = tid; i < 3 * 128 * 32; i += NT) {
            const int g  = i >> 12;
            const int r_ = i & 4095;
            const int kp = r_ >> 5;
            const int jj = r_ & 31;
            const float* G = Ws[g];
            sW64[i] = pk(G[(2 * kp) * HH + jbase + jj],
                         G[(2 * kp + 1) * HH + jbase + jj]);
        }
    }
    // ---- h0 into parity-0 buffer; x(0) staged ----
    sH[tid]      = h0[b0 * HH + tid];
    sH[HH + tid] = h0[b1 * HH + tid];
    sX[tid]      = x[(size_t)b0 * SS * EE + tid];
    sX[EE + tid] = x[(size_t)b1 * SS * EE + tid];
    if (tid == 0) {
        mbar_init(mb_rh, 1); mbar_init(mb_rh + 8, 1);
        mbar_init(mb_h, 1);  mbar_init(mb_h + 8, 1);
    }
    __syncthreads();
    cluster_sync_();

    float px0 = x[((size_t)b0 * SS + 1) * EE + tid];
    float px1 = x[((size_t)b1 * SS + 1) * EE + tid];

    const u64* Wz64 = sW64 + 0 * 4096 + j;   // + kp*32
    const u64* Wr64 = sW64 + 1 * 4096 + j;
    const u64* Wh64 = sW64 + 2 * 4096 + j;

    for (int t = 0; t < SS; t++) {
        const int par = t & 1;
        const int nxt = par ^ 1;
        float* shA  = sH  + par * (NB * HH);
        float* srhA = sRH + par * (NB * HH);
        const u64* X64 = (const u64*)(sX + par * (NB * EE));  // [b*128 + kp]
        const u64* H64 = (const u64*)shA;
        const u64* R64 = (const u64*)srhA;

        if (tid == 0) {
            mbar_expect(mb_rh + par * 8, NB * HH * 4);
            if (t + 1 < SS) mbar_expect(mb_h + nxt * 8, NB * HH * 4);
        }

        // ---- phase 1: x @ {Wz, Wr} (independent of h -> hides h flight) ----
        u64 az0 = 0, az1 = 0, ar0 = 0, ar1 = 0;
#pragma unroll
        for (int p = 0; p < 16; p++) {
            const int kp = ksk + p;
            const u64 xa = X64[kp], xb = X64[128 + kp];
            const u64 wz = Wz64[kp * 32], wr = Wr64[kp * 32];
            ffma2(az0, xa, wz); ffma2(az1, xb, wz);
            ffma2(ar0, xa, wr); ffma2(ar1, xb, wr);
        }

        if (t > 0) mbar_wait(mb_h + par * 8, (uint32_t)(((t - 2 + par) >> 1) & 1));

        // ---- phase 3: h @ {Uz, Ur} (U in registers) ----
#pragma unroll
        for (int p = 0; p < 16; p++) {
            const int kp = ksk + p;
            const u64 ha = H64[kp], hb = H64[128 + kp];
            ffma2(az0, ha, uz2[p]); ffma2(az1, hb, uz2[p]);
            ffma2(ar0, ha, ur2[p]); ffma2(ar1, hb, ur2[p]);
        }
        sP[tid]       = hsum(az0);
        sP[256 + tid] = hsum(az1);
        sP[512 + tid] = hsum(ar0);
        sP[768 + tid] = hsum(ar1);
        __syncthreads();

        // ---- mid reduce: z kept local, r*h pushed cluster-wide (b64) ----
        if (tid < 128) {
            const int mb = tid >> 5, jj = tid & 31;
            float s = 0.f;
#pragma unroll
            for (int q = 0; q < 8; q++) s += sP[mb * 256 + q * 32 + jj];
            const float g = __fdividef(1.f, 1.f + __expf(-s));
            if (mb < 2) {
                sZ[mb * 32 + jj] = g;
            } else {
                const int b = mb - 2;
                const float rh  = g * shA[b * HH + jbase + jj];
                const float rhh = __shfl_down_sync(0xffffffffu, rh, 1);
                if ((jj & 1) == 0) {
                    const uint32_t off =
                        (uint32_t)(OFF_RH + par * (NB * HH) + b * HH + jbase + jj) * 4;
                    push8_b64(base_u, off, pk(rh, rhh),
                              (uint32_t)(OFF_MB * 4) + (uint32_t)(par * 8));
                }
            }
        }

        // ---- phase 5: x @ Wh (independent of rh -> hides rh flight) ----
        u64 ah0 = 0, ah1 = 0;
#pragma unroll
        for (int p = 0; p < 16; p++) {
            const int kp = ksk + p;
            const u64 xa = X64[kp], xb = X64[128 + kp];
            const u64 wh = Wh64[kp * 32];
            ffma2(ah0, xa, wh); ffma2(ah1, xb, wh);
        }

        mbar_wait(mb_rh + par * 8, (uint32_t)((t >> 1) & 1));

        // ---- phase 7: (r*h) @ Uh (U in registers) ----
#pragma unroll
        for (int p = 0; p < 16; p++) {
            const int kp = ksk + p;
            const u64 ra = R64[kp], rb = R64[128 + kp];
            ffma2(ah0, ra, uh2[p]); ffma2(ah1, rb, uh2[p]);
        }
        sP[1024 + tid] = hsum(ah0);
        sP[1280 + tid] = hsum(ah1);
        // stage x(t+1) into the other parity buffer
        if (t + 1 < SS) {
            sX[nxt * (NB * EE) + tid]      = px0;
            sX[nxt * (NB * EE) + EE + tid] = px1;
        }
        __syncthreads();

        // ---- final: tanh, combine, output, push h(t+1) ----
        if (tid < 64) {
            const int b = tid >> 5, jj = tid & 31;
            float s = 0.f;
#pragma unroll
            for (int q = 0; q < 8; q++) s += sP[1024 + b * 256 + q * 32 + jj];
            const float hw   = 1.f - __fdividef(2.f, __expf(2.f * s) + 1.f);
            const float z    = sZ[b * 32 + jj];
            const float hold = shA[b * HH + jbase + jj];
            const float hnew = fmaf(z, hw - hold, hold);
            out[((size_t)(b0 + b) * SS + t) * HH + jbase + jj] = hnew;
            if (t + 1 < SS) {
                const float hh = __shfl_down_sync(0xffffffffu, hnew, 1);
                if ((jj & 1) == 0) {
                    const uint32_t off =
                        (uint32_t)(OFF_H + nxt * (NB * HH) + b * HH + jbase + jj) * 4;
                    push8_b64(base_u, off, pk(hnew, hh),
                              (uint32_t)(OFF_MB * 4 + 16) + (uint32_t)(nxt * 8));
                }
            }
        }
        // prefetch x(t+2)
        if (t + 2 < SS) {
            px0 = x[((size_t)b0 * SS + t + 2) * EE + tid];
            px1 = x[((size_t)b1 * SS + t + 2) * EE + tid];
        }
    }
    cluster_sync_();   // no CTA exits while inbound traffic could be in flight
}

extern "C" void kernel_launch(void* const* d_in, const int* in_sizes, int n_in,
                              void* d_out, int out_size)
{
    (void)in_sizes; (void)n_in; (void)out_size;
    const float* x  = (const float*)d_in[0];
    const float* h0 = (const float*)d_in[1];
    const float* Wz = (const float*)d_in[2];
    const float* Uz = (const float*)d_in[3];
    const float* Wr = (const float*)d_in[4];
    const float* Ur = (const float*)d_in[5];
    const float* Wh = (const float*)d_in[6];
    const float* Uh = (const float*)d_in[7];
    float* out = (float*)d_out;

    cudaFuncSetAttribute(gru_persistent,
                         cudaFuncAttributeMaxDynamicSharedMemorySize, SMEM_BYTES);
    gru_persistent<<<GRID, NT, SMEM_BYTES>>>(x, h0, Wz, Uz, Wr, Ur, Wh, Uh, out);
}

// round 11
// speedup vs baseline: 1.8940x; 1.0020x over previous
#include <cuda_runtime.h>
#include <cstdint>
#include <math.h>

// GRU: B=32, S=2048, E=256, H=256, fp32.
// Kernel 1: precompute gate inputs xg = x @ {Wz,Wr,Wh} (3 GEMMs, f32x2).
// Kernel 2: persistent scan. 16 groups x 8-CTA cluster; CTA owns 32-wide H slice.
// U matrices in registers; gate inputs streamed from gmem with 1-step prefetch.
// h / r*h exchanged via st.async.b64 + double-buffered mbarrier tx accounting.

#define SS   2048
#define EE   256
#define HH   256
#define CSZ  8
#define NB   2
#define NT   256
#define NGRP 16
#define GRID (NGRP * CSZ)
#define GM   (32 * 2048)          // rows per gate matrix

typedef unsigned long long u64;

// scratch: xg[3][GM][256]  (g, b*S+t, h)  = 192 MB
__device__ float g_gates[(size_t)3 * GM * HH];

// ---------------- common helpers ----------------
__device__ __forceinline__ uint32_t smem_u32(const void* p) {
    uint32_t a;
    asm("{ .reg .u64 t; cvta.to.shared.u64 t, %1; cvt.u32.u64 %0, t; }"
        : "=r"(a) : "l"(p));
    return a;
}
__device__ __forceinline__ void mbar_init(uint32_t a, uint32_t cnt) {
    asm volatile("mbarrier.init.shared.b64 [%0], %1;" :: "r"(a), "r"(cnt) : "memory");
}
__device__ __forceinline__ void mbar_expect(uint32_t a, uint32_t bytes) {
    asm volatile("mbarrier.arrive.expect_tx.shared.b64 _, [%0], %1;"
                 :: "r"(a), "r"(bytes) : "memory");
}
__device__ __forceinline__ void mbar_wait(uint32_t a, uint32_t parity) {
    asm volatile(
        "{\n\t.reg .pred P1;\n\t"
        "WL_%=:\n\t"
        "mbarrier.try_wait.parity.acquire.cta.shared::cta.b64 P1, [%0], %1, 0x989680;\n\t"
        "@P1 bra.uni WD_%=;\n\t"
        "bra.uni WL_%=;\n\t"
        "WD_%=:\n\t}"
        :: "r"(a), "r"(parity) : "memory");
}
__device__ __forceinline__ void cluster_sync_() {
    asm volatile("barrier.cluster.arrive.aligned;" ::: "memory");
    asm volatile("barrier.cluster.wait.aligned;"  ::: "memory");
}
__device__ __forceinline__ u64 pk(float lo, float hi) {
    u64 r; asm("mov.b64 %0, {%1, %2};" : "=l"(r) : "f"(lo), "f"(hi)); return r;
}
__device__ __forceinline__ float hsum(u64 v) {
    float a, b; asm("mov.b64 {%0, %1}, %2;" : "=f"(a), "=f"(b) : "l"(v));
    return a + b;
}
__device__ __forceinline__ void ffma2(u64& d, u64 a, u64 b) {
    asm("fma.rn.f32x2 %0, %1, %2, %0;" : "+l"(d) : "l"(a), "l"(b));
}
__device__ __forceinline__ void push8_b64(uint32_t base_u, uint32_t off_b,
                                          u64 v, uint32_t moff_b) {
#pragma unroll
    for (int r = 0; r < CSZ; r++) {
        uint32_t ra;
        asm volatile("mapa.shared::cluster.u32 %0, %1, %2;"
                     : "=r"(ra) : "r"(base_u), "r"(r));
        asm volatile("st.async.shared::cluster.mbarrier::complete_tx::bytes.b64 "
                     "[%0], %1, [%2];"
                     :: "r"(ra + off_b), "l"(v), "r"(ra + moff_b) : "memory");
    }
}

// ================= Kernel 1: gate-input GEMMs =================
// C[g] = X[65536,256] @ Wg[256,256].  Tile 128 rows x 64 cols, K-chunk 32.
// grid = (512, 12): y = g*4 + ntile.
__global__ void __launch_bounds__(256)
gru_gemm(const float* __restrict__ x, const float* __restrict__ Wz,
         const float* __restrict__ Wr, const float* __restrict__ Wh)
{
    __shared__ float sA[32][128];   // k-major (transposed) for LDS.128 a-loads
    __shared__ float sB[32][64];

    const int mt = blockIdx.x;            // 0..511
    const int gy = blockIdx.y;            // 0..11
    const int g  = gy >> 2, nt = gy & 3;
    const float* W = (g == 0) ? Wz : (g == 1) ? Wr : Wh;
    const int row0 = mt * 128, col0 = nt * 64;

    const int tid = threadIdx.x;
    const int tx = tid & 15;              // 4 cols (2 u64)
    const int ty = tid >> 4;              // 8 rows

    u64 acc[8][2];
#pragma unroll
    for (int i = 0; i < 8; i++) { acc[i][0] = 0; acc[i][1] = 0; }

    for (int kc = 0; kc < 8; kc++) {
        // load A tile 128x32 -> transposed sA[k][row]
#pragma unroll
        for (int q = 0; q < 4; q++) {
            const int fi = tid + q * 256;          // 0..1023 float4s
            const int r  = fi >> 3, c = fi & 7;    // row r, f4-col c
            const float4 v = *(const float4*)&x[(size_t)(row0 + r) * EE + kc * 32 + c * 4];
            sA[c * 4 + 0][r] = v.x;
            sA[c * 4 + 1][r] = v.y;
            sA[c * 4 + 2][r] = v.z;
            sA[c * 4 + 3][r] = v.w;
        }
        // load B tile 32x64
#pragma unroll
        for (int q = 0; q < 2; q++) {
            const int fi = tid + q * 256;          // 0..511 float4s
            const int r  = fi >> 4, c = fi & 15;
            *(float4*)&sB[r][c * 4] =
                *(const float4*)&W[(size_t)(kc * 32 + r) * HH + col0 + c * 4];
        }
        __syncthreads();
#pragma unroll 8
        for (int k = 0; k < 32; k++) {
            const float4 a0 = *(const float4*)&sA[k][ty * 8];
            const float4 a1 = *(const float4*)&sA[k][ty * 8 + 4];
            const u64 b0 = *(const u64*)&sB[k][tx * 4];
            const u64 b1 = *(const u64*)&sB[k][tx * 4 + 2];
            const float av[8] = {a0.x, a0.y, a0.z, a0.w, a1.x, a1.y, a1.z, a1.w};
#pragma unroll
            for (int i = 0; i < 8; i++) {
                const u64 a2 = pk(av[i], av[i]);
                ffma2(acc[i][0], a2, b0);
                ffma2(acc[i][1], a2, b1);
            }
        }
        __syncthreads();
    }
    // store
#pragma unroll
    for (int i = 0; i < 8; i++) {
        const size_t idx = ((size_t)g * GM + row0 + ty * 8 + i) * HH + col0 + tx * 4;
        *(u64*)&g_gates[idx]     = acc[i][0];
        *(u64*)&g_gates[idx + 2] = acc[i][1];
    }
}

// ================= Kernel 2: persistent scan =================
// smem layout (floats)
#define OFF_H   0                  // [2][NB][HH] = 1024
#define OFF_RH  1024               // [2][NB][HH] = 1024
#define OFF_P   2048               // [6][256]    = 1536
#define OFF_MB  3584               // 4 mbarriers = 8 floats
#define SMEM_FLOATS (OFF_MB + 8)
#define SMEM_BYTES  (SMEM_FLOATS * 4)

extern __shared__ float smem[];

__global__ void __cluster_dims__(CSZ, 1, 1) __launch_bounds__(NT, 1)
gru_scan(const float* __restrict__ h0,
         const float* __restrict__ Uz, const float* __restrict__ Ur,
         const float* __restrict__ Uh, float* __restrict__ out)
{
    const int tid   = threadIdx.x;
    const int rank  = blockIdx.x & (CSZ - 1);
    const int grp   = blockIdx.x >> 3;
    const int b0    = grp * NB;
    const int jbase = rank * 32;
    const int j     = tid & 31;
    const int ks    = tid >> 5;
    const int k0    = ks * 32;
    const int jcol  = jbase + j;

    float* sH  = smem + OFF_H;
    float* sRH = smem + OFF_RH;
    float* sP  = smem + OFF_P;

    const uint32_t base_u = smem_u32(smem);
    const uint32_t mb_rh  = base_u + OFF_MB * 4;        // +par*8
    const uint32_t mb_h   = base_u + OFF_MB * 4 + 16;   // +par*8

    // ---- U slices into registers (k-pairs packed for FFMA2): 48 u64 ----
    u64 uz2[16], ur2[16], uh2[16];
#pragma unroll
    for (int p = 0; p < 16; p++) {
        const int k = k0 + 2 * p;
        uz2[p] = pk(Uz[k * HH + jcol], Uz[(k + 1) * HH + jcol]);
        ur2[p] = pk(Ur[k * HH + jcol], Ur[(k + 1) * HH + jcol]);
        uh2[p] = pk(Uh[k * HH + jcol], Uh[(k + 1) * HH + jcol]);
    }
    // ---- h0 into parity-0 buffer ----
    sH[tid]      = h0[b0 * HH + tid];
    sH[HH + tid] = h0[(b0 + 1) * HH + tid];
    if (tid == 0) {
        mbar_init(mb_rh, 1); mbar_init(mb_rh + 8, 1);
        mbar_init(mb_h, 1);  mbar_init(mb_h + 8, 1);
    }
    __syncthreads();
    cluster_sync_();

    // ---- gate-input prefetch (role-partitioned) ----
    // tid 0-63      : r-reduce  -> pre_r  (b=tid>>5, jj=tid&31)
    // tid 128-191   : combine   -> pre_z, pre_h
    float pre_r = 0.f, pre_z = 0.f, pre_h = 0.f;
    if (tid < 64) {
        const int b = tid >> 5, jj = tid & 31;
        pre_r = g_gates[((size_t)1 * GM + (size_t)(b0 + b) * SS) * HH + jbase + jj];
    } else if (tid >= 128 && tid < 192) {
        const int b = (tid - 128) >> 5, jj = tid & 31;
        pre_z = g_gates[((size_t)0 * GM + (size_t)(b0 + b) * SS) * HH + jbase + jj];
        pre_h = g_gates[((size_t)2 * GM + (size_t)(b0 + b) * SS) * HH + jbase + jj];
    }

    for (int t = 0; t < SS; t++) {
        const int par = t & 1;
        const int nxt = par ^ 1;
        float* shA  = sH  + par * (NB * HH);
        float* srhA = sRH + par * (NB * HH);
        const float4* Hc = (const float4*)shA;
        const float4* Rc = (const float4*)srhA;

        if (tid == 0) {
            mbar_expect(mb_rh + par * 8, NB * HH * 4);
            if (t + 1 < SS) mbar_expect(mb_h + nxt * 8, NB * HH * 4);
        }
        if (t > 0) mbar_wait(mb_h + par * 8, (uint32_t)(((t - 2 + par) >> 1) & 1));

        // ---- phase R: h @ Ur ----
        u64 ar0 = 0, ar1 = 0;
#pragma unroll
        for (int q = 0; q < 8; q++) {
            const float4 ha = Hc[ks * 8 + q], hb = Hc[64 + ks * 8 + q];
            const u64 ha0 = pk(ha.x, ha.y), ha1 = pk(ha.z, ha.w);
            const u64 hb0 = pk(hb.x, hb.y), hb1 = pk(hb.z, hb.w);
            ffma2(ar0, ha0, ur2[2 * q]); ffma2(ar0, ha1, ur2[2 * q + 1]);
            ffma2(ar1, hb0, ur2[2 * q]); ffma2(ar1, hb1, ur2[2 * q + 1]);
        }
        sP[tid]       = hsum(ar0);
        sP[256 + tid] = hsum(ar1);
        __syncthreads();

        // ---- r reduce + push r*h ----
        if (tid < 64) {
            const int b = tid >> 5, jj = tid & 31;
            float s = pre_r;
#pragma unroll
            for (int q = 0; q < 8; q++) s += sP[b * 256 + q * 32 + jj];
            const float r  = __fdividef(1.f, 1.f + __expf(-s));
            const float rh = r * shA[b * HH + jbase + jj];
            const float rhh = __shfl_down_sync(0xffffffffu, rh, 1);
            if ((jj & 1) == 0) {
                const uint32_t off =
                    (uint32_t)(OFF_RH + par * (NB * HH) + b * HH + jbase + jj) * 4;
                push8_b64(base_u, off, pk(rh, rhh),
                          (uint32_t)(OFF_MB * 4) + (uint32_t)(par * 8));
            }
            if (t + 1 < SS)
                pre_r = g_gates[((size_t)1 * GM + (size_t)(b0 + b) * SS + t + 1) * HH
                                + jbase + jj];
        }

        // ---- phase Z: h @ Uz (hides rh flight) ----
        u64 az0 = 0, az1 = 0;
#pragma unroll
        for (int q = 0; q < 8; q++) {
            const float4 ha = Hc[ks * 8 + q], hb = Hc[64 + ks * 8 + q];
            const u64 ha0 = pk(ha.x, ha.y), ha1 = pk(ha.z, ha.w);
            const u64 hb0 = pk(hb.x, hb.y), hb1 = pk(hb.z, hb.w);
            ffma2(az0, ha0, uz2[2 * q]); ffma2(az0, ha1, uz2[2 * q + 1]);
            ffma2(az1, hb0, uz2[2 * q]); ffma2(az1, hb1, uz2[2 * q + 1]);
        }
        sP[512 + tid] = hsum(az0);
        sP[768 + tid] = hsum(az1);

        mbar_wait(mb_rh + par * 8, (uint32_t)((t >> 1) & 1));

        // ---- phase H: (r*h) @ Uh ----
        u64 ah0 = 0, ah1 = 0;
#pragma unroll
        for (int q = 0; q < 8; q++) {
            const float4 ra = Rc[ks * 8 + q], rb = Rc[64 + ks * 8 + q];
            const u64 ra0 = pk(ra.x, ra.y), ra1 = pk(ra.z, ra.w);
            const u64 rb0 = pk(rb.x, rb.y), rb1 = pk(rb.z, rb.w);
            ffma2(ah0, ra0, uh2[2 * q]); ffma2(ah0, ra1, uh2[2 * q + 1]);
            ffma2(ah1, rb0, uh2[2 * q]); ffma2(ah1, rb1, uh2[2 * q + 1]);
        }
        sP[1024 + tid] = hsum(ah0);
        sP[1280 + tid] = hsum(ah1);
        __syncthreads();

        // ---- combine: z, h~, output, push h(t+1) ----
        if (tid >= 128 && tid < 192) {
            const int b = (tid - 128) >> 5, jj = tid & 31;
            float sz = pre_z, sh = pre_h;
#pragma unroll
            for (int q = 0; q < 8; q++) {
                sz += sP[(2 + b) * 256 + q * 32 + jj];
                sh += sP[(4 + b) * 256 + q * 32 + jj];
            }
            const float z    = __fdividef(1.f, 1.f + __expf(-sz));
            const float hw   = 1.f - __fdividef(2.f, __expf(2.f * sh) + 1.f);
            const float hold = shA[b * HH + jbase + jj];
            const float hnew = fmaf(z, hw - hold, hold);
            out[((size_t)(b0 + b) * SS + t) * HH + jbase + jj] = hnew;
            if (t + 1 < SS) {
                const float hh = __shfl_down_sync(0xffffffffu, hnew, 1);
                if ((jj & 1) == 0) {
                    const uint32_t off =
                        (uint32_t)(OFF_H + nxt * (NB * HH) + b * HH + jbase + jj) * 4;
                    push8_b64(base_u, off, pk(hnew, hh),
                              (uint32_t)(OFF_MB * 4 + 16) + (uint32_t)(nxt * 8));
                }
                pre_z = g_gates[((size_t)0 * GM + (size_t)(b0 + b) * SS + t + 1) * HH
                                + jbase + jj];
                pre_h = g_gates[((size_t)2 * GM + (size_t)(b0 + b) * SS + t + 1) * HH
                                + jbase + jj];
            }
        }
    }
    cluster_sync_();   // no CTA exits while inbound traffic could be in flight
}

extern "C" void kernel_launch(void* const* d_in, const int* in_sizes, int n_in,
                              void* d_out, int out_size)
{
    (void)in_sizes; (void)n_in; (void)out_size;
    const float* x  = (const float*)d_in[0];
    const float* h0 = (const float*)d_in[1];
    const float* Wz = (const float*)d_in[2];
    const float* Uz = (const float*)d_in[3];
    const float* Wr = (const float*)d_in[4];
    const float* Ur = (const float*)d_in[5];
    const float* Wh = (const float*)d_in[6];
    const float* Uh = (const float*)d_in[7];
    float* out = (float*)d_out;

    dim3 ggrid(512, 12);
    gru_gemm<<<ggrid, 256>>>(x, Wz, Wr, Wh);

    cudaFuncSetAttribute(gru_scan,
                         cudaFuncAttributeMaxDynamicSharedMemorySize, SMEM_BYTES);
    gru_scan<<<GRID, NT, SMEM_BYTES>>>(h0, Uz, Ur, Uh, out);
}